// round 2
// baseline (speedup 1.0000x reference)
#include <cuda_runtime.h>
#include <math.h>

#define IMN 4096
#define NPIX (IMN*IMN)
#define MED_RANK 8388607u   /* (NPIX-1)/2 */

// ---------------- device scratch (no allocations allowed) ----------------
__device__ float    g_R[NPIX];          // Harris response
__device__ unsigned g_cand[NPIX];       // pass-2 compacted candidate keys
__device__ unsigned g_hist[8192];       // radix-select histogram (reused per pass)
__device__ unsigned g_ncand;            // candidate count
__device__ unsigned g_prefix;           // accumulated key prefix
__device__ unsigned g_rank;             // remaining rank
__device__ float    g_med;              // selected median value

// monotonic float<->uint order transform
__device__ __forceinline__ unsigned f2u(float f) {
    unsigned u = __float_as_uint(f);
    return (u & 0x80000000u) ? ~u : (u | 0x80000000u);
}
__device__ __forceinline__ float u2f(unsigned u) {
    return (u & 0x80000000u) ? __uint_as_float(u & 0x7fffffffu)
                             : __uint_as_float(~u);
}

// ---------------- init ----------------
__global__ void k_init() {
    int t = threadIdx.x;
    for (int b = t; b < 8192; b += 256) g_hist[b] = 0u;
    if (t == 0) { g_prefix = 0u; g_rank = MED_RANK; g_med = 0.0f; g_ncand = 0u; }
}

// ---------------- fused Sobel + products + 7x7 Gaussian -> R + pass-1 hist --
// 32x32 output tile, halo 4 (1 sobel + 3 gaussian). 256 threads.
__global__ __launch_bounds__(256) void k_R(const float* __restrict__ x,
                                           const float* __restrict__ gk) {
    __shared__ union {
        struct {
            float sx [40][41];
            float sIx[38][39];
            float sIy[38][39];
            float sh [3][38][33];
        } s;
        unsigned hist[8192];
    } u_;

    const int tid = threadIdx.x;
    const int bx = blockIdx.x * 32, by = blockIdx.y * 32;

    // 1D gaussian factors from provided 2D kernel: w[k] = g2[3][k]/sqrt(g2[3][3])
    float winv = rsqrtf(gk[24]);
    float w[7];
#pragma unroll
    for (int k = 0; k < 7; k++) w[k] = gk[21 + k] * winv;

    // stage 0: load x tile with zero padding
    for (int i = tid; i < 40 * 40; i += 256) {
        int r = i / 40, c = i % 40;
        int gy = by - 4 + r, gx = bx - 4 + c;
        float v = 0.0f;
        if ((unsigned)gy < IMN && (unsigned)gx < IMN) v = x[gy * IMN + gx];
        u_.s.sx[r][c] = v;
    }
    __syncthreads();

    // stage 1: Sobel (cross-correlation) on 38x38 region; zero outside image
    for (int i = tid; i < 38 * 38; i += 256) {
        int r = i / 38, c = i % 38;
        int gy = by - 3 + r, gx = bx - 3 + c;
        float ix = 0.0f, iy = 0.0f;
        if ((unsigned)gy < IMN && (unsigned)gx < IMN) {
            float a  = u_.s.sx[r    ][c], b = u_.s.sx[r    ][c + 1], cc = u_.s.sx[r    ][c + 2];
            float d  = u_.s.sx[r + 1][c],                            f  = u_.s.sx[r + 1][c + 2];
            float g  = u_.s.sx[r + 2][c], h = u_.s.sx[r + 2][c + 1], i2 = u_.s.sx[r + 2][c + 2];
            ix = (cc - a) + 2.0f * (f - d) + (i2 - g);
            iy = (g + 2.0f * h + i2) - (a + 2.0f * b + cc);
        }
        u_.s.sIx[r][c] = ix;
        u_.s.sIy[r][c] = iy;
    }
    __syncthreads();

    // stage 2: horizontal 7-tap gaussian of the 3 products
    for (int i = tid; i < 38 * 32; i += 256) {
        int r = i / 32, c = i % 32;
        float s0 = 0.0f, s1 = 0.0f, s2 = 0.0f;
#pragma unroll
        for (int k = 0; k < 7; k++) {
            float a = u_.s.sIx[r][c + k], b = u_.s.sIy[r][c + k], wk = w[k];
            s0 = fmaf(wk, a * a, s0);
            s1 = fmaf(wk, b * b, s1);
            s2 = fmaf(wk, a * b, s2);
        }
        u_.s.sh[0][r][c] = s0; u_.s.sh[1][r][c] = s1; u_.s.sh[2][r][c] = s2;
    }
    __syncthreads();

    // stage 3: vertical 7-tap gaussian + Harris response (keep keys in regs)
    const int tx = tid & 31, ty = tid >> 5;
    unsigned uk[4];
#pragma unroll
    for (int j = 0; j < 4; j++) {
        int r = ty * 4 + j;
        float a0 = 0.0f, a1 = 0.0f, a2 = 0.0f;
#pragma unroll
        for (int k = 0; k < 7; k++) {
            float wk = w[k];
            a0 = fmaf(wk, u_.s.sh[0][r + k][tx], a0);
            a1 = fmaf(wk, u_.s.sh[1][r + k][tx], a1);
            a2 = fmaf(wk, u_.s.sh[2][r + k][tx], a2);
        }
        float tr = a0 + a1;
        float R  = (a0 * a1 - a2 * a2) - 0.05f * tr * tr;
        g_R[(by + r) * IMN + (bx + tx)] = R;
        uk[j] = f2u(R);
    }
    __syncthreads();   // all reads of sh done -> safe to overlay hist

    // fused pass-1 histogram: top 13 bits
    for (int b = tid; b < 8192; b += 256) u_.hist[b] = 0u;
    __syncthreads();
#pragma unroll
    for (int j = 0; j < 4; j++) atomicAdd(&u_.hist[uk[j] >> 19], 1u);
    __syncthreads();
    for (int b = tid; b < 8192; b += 256) {
        unsigned c = u_.hist[b];
        if (c) atomicAdd(&g_hist[b], c);
    }
}

// ---------------- parallel radix-select over 8192 bins (single block) ------
__global__ __launch_bounds__(256) void k_select(int shift) {
    const int tid = threadIdx.x;
    const unsigned rank = g_rank;
    const unsigned pref = g_prefix;

    unsigned cnt[32];
    unsigned s = 0u;
#pragma unroll
    for (int j = 0; j < 32; j++) { cnt[j] = g_hist[tid * 32 + j]; s += cnt[j]; }

    // block-wide exclusive scan of s
    unsigned v = s;
    const int lane = tid & 31, wid = tid >> 5;
#pragma unroll
    for (int o = 1; o < 32; o <<= 1) {
        unsigned t = __shfl_up_sync(0xFFFFFFFFu, v, o);
        if (lane >= o) v += t;
    }
    __shared__ unsigned wsum[8];
    if (lane == 31) wsum[wid] = v;
    __syncthreads();
    if (tid < 8) {
        unsigned t = wsum[tid];
#pragma unroll
        for (int o = 1; o < 8; o <<= 1) {
            unsigned q = __shfl_up_sync(0xFFu, t, o);
            if (tid >= o) t += q;
        }
        wsum[tid] = t;
    }
    __syncthreads();
    unsigned incl   = v + (wid ? wsum[wid - 1] : 0u);
    unsigned before = incl - s;

    if (s > 0u && rank >= before && rank < incl) {
        unsigned run = before;
#pragma unroll
        for (int j = 0; j < 32; j++) {
            if (rank < run + cnt[j]) {
                g_prefix = pref | ((unsigned)(tid * 32 + j) << shift);
                g_rank   = rank - run;
                break;
            }
            run += cnt[j];
        }
    }
    __syncthreads();
    for (int b = tid; b < 8192; b += 256) g_hist[b] = 0u;
}

// ---------------- pass-2 histogram + candidate compaction ------------------
__global__ __launch_bounds__(256) void k_hist2() {
    __shared__ unsigned h[8192];
    for (int b = threadIdx.x; b < 8192; b += 256) h[b] = 0u;
    __syncthreads();

    const unsigned pref = g_prefix;        // top 13 bits << 19
    const float4* R4 = (const float4*)g_R;
    const int n4 = NPIX / 4;
    const int stride = gridDim.x * blockDim.x;
    const int lane = threadIdx.x & 31;

    for (int i = blockIdx.x * blockDim.x + threadIdx.x; i < n4; i += stride) {
        float4 v = R4[i];
        unsigned uu[4] = { f2u(v.x), f2u(v.y), f2u(v.z), f2u(v.w) };
#pragma unroll
        for (int j = 0; j < 4; j++) {
            bool m = (uu[j] & 0xFFF80000u) == pref;
            unsigned bal = __ballot_sync(0xFFFFFFFFu, m);   // n4 % 32 == 0: warps uniform
            if (m) {
                atomicAdd(&h[(uu[j] >> 6) & 8191u], 1u);
                int leader = __ffs(bal) - 1;
                unsigned base;
                if (lane == leader) base = atomicAdd(&g_ncand, (unsigned)__popc(bal));
                base = __shfl_sync(bal, base, leader);
                g_cand[base + __popc(bal & ((1u << lane) - 1u))] = uu[j];
            }
        }
    }
    __syncthreads();
    for (int b = threadIdx.x; b < 8192; b += 256) {
        unsigned c = h[b];
        if (c) atomicAdd(&g_hist[b], c);
    }
}

// ---------------- final pass: 64-bin hist over candidates + select ---------
__global__ __launch_bounds__(1024) void k_final() {
    __shared__ unsigned h[64];
    const int tid = threadIdx.x;
    if (tid < 64) h[tid] = 0u;
    __syncthreads();

    const unsigned pref = g_prefix;        // bits [31:6]
    const unsigned n = g_ncand;
    for (unsigned i = tid; i < n; i += 1024) {
        unsigned u = g_cand[i];
        if ((u & 0xFFFFFFC0u) == pref) atomicAdd(&h[u & 63u], 1u);
    }
    __syncthreads();
    if (tid == 0) {
        unsigned rank = g_rank, run = 0u;
        for (int b = 0; b < 64; b++) {
            unsigned c = h[b];
            if (rank < run + c) { g_med = u2f(pref | (unsigned)b); break; }
            run += c;
        }
    }
}

// ---------------- fused threshold + 7x7 NMS maxpool + mask ----------------
__global__ __launch_bounds__(256) void k_nms(float* __restrict__ out) {
    __shared__ float sr[38][40];
    __shared__ float hm[38][33];
    const int tid = threadIdx.x;
    const int bx = blockIdx.x * 32, by = blockIdx.y * 32;
    const float med = g_med;

    for (int i = tid; i < 38 * 38; i += 256) {
        int r = i / 38, c = i % 38;
        int gy = by - 3 + r, gx = bx - 3 + c;
        float v = -INFINITY;
        if ((unsigned)gy < IMN && (unsigned)gx < IMN) {
            float q = g_R[gy * IMN + gx];
            v = (q < med) ? 0.0f : q;
        }
        sr[r][c] = v;
    }
    __syncthreads();

    for (int i = tid; i < 38 * 32; i += 256) {
        int r = i / 32, c = i % 32;
        float m = sr[r][c];
#pragma unroll
        for (int k = 1; k < 7; k++) m = fmaxf(m, sr[r][c + k]);
        hm[r][c] = m;
    }
    __syncthreads();

    const int tx = tid & 31, ty = tid >> 5;
#pragma unroll
    for (int j = 0; j < 4; j++) {
        int r = ty * 4 + j;
        float m = hm[r][tx];
#pragma unroll
        for (int k = 1; k < 7; k++) m = fmaxf(m, hm[r + k][tx]);
        float ctr = sr[r + 3][tx + 3];
        out[(by + r) * IMN + (bx + tx)] = (ctr == m) ? ctr : 0.0f;
    }
}

// ---------------- launch ----------------
extern "C" void kernel_launch(void* const* d_in, const int* in_sizes, int n_in,
                              void* d_out, int out_size) {
    const float* x  = (const float*)d_in[0];
    const float* gk = (const float*)d_in[1];
    float* out = (float*)d_out;

    dim3 grid(IMN / 32, IMN / 32);

    k_init<<<1, 256>>>();
    k_R<<<grid, 256>>>(x, gk);           // fused: R + pass-1 hist (bits [31:19])
    k_select<<<1, 256>>>(19);
    k_hist2<<<1184, 256>>>();            // pass-2 hist (bits [18:6]) + compaction
    k_select<<<1, 256>>>(6);
    k_final<<<1, 1024>>>();              // bits [5:0] over compacted candidates
    k_nms<<<grid, 256>>>(out);
}

// round 3
// speedup vs baseline: 2.0694x; 2.0694x over previous
#include <cuda_runtime.h>
#include <math.h>

#define IMN 4096
#define NPIX (IMN*IMN)
#define MED_RANK 8388607u   /* (NPIX-1)/2 */

// ---------------- device scratch (no allocations allowed) ----------------
__device__ float    g_R[NPIX];            // Harris response
__device__ unsigned g_hist13[8192];       // pass-1 histogram (top 13 bits)
__device__ unsigned g_hist19[1 << 19];    // pass-2 histogram (low 19 bits)
__device__ unsigned g_chunk[512];         // chunk sums for 19-bit select
__device__ unsigned g_prefix;             // selected top-13-bit bin
__device__ unsigned g_rank;               // remaining rank
__device__ float    g_med;                // selected median value

// monotonic float<->uint order transform
__device__ __forceinline__ unsigned f2u(float f) {
    unsigned u = __float_as_uint(f);
    return (u & 0x80000000u) ? ~u : (u | 0x80000000u);
}
__device__ __forceinline__ float u2f(unsigned u) {
    return (u & 0x80000000u) ? __uint_as_float(u & 0x7fffffffu)
                             : __uint_as_float(~u);
}

// ---------------- init: zero both histograms ----------------
__global__ void k_init() {
    int gt = blockIdx.x * blockDim.x + threadIdx.x;
    int stride = gridDim.x * blockDim.x;
    for (int b = gt; b < (1 << 19); b += stride) g_hist19[b] = 0u;
    for (int b = gt; b < 8192; b += stride) g_hist13[b] = 0u;
    if (gt == 0) { g_prefix = 0u; g_rank = MED_RANK; g_med = 0.0f; }
}

// ---------------- fused Sobel + products + 7x7 Gaussian -> R ----------------
// 32x32 output tile, halo 4 (1 sobel + 3 gaussian). 256 threads.
__global__ __launch_bounds__(256) void k_R(const float* __restrict__ x,
                                           const float* __restrict__ gk) {
    __shared__ float sx [40][41];
    __shared__ float sIx[38][39];
    __shared__ float sIy[38][39];
    __shared__ float sh [3][38][33];

    const int tid = threadIdx.x;
    const int bx = blockIdx.x * 32, by = blockIdx.y * 32;

    // 1D gaussian factors from provided 2D kernel: w[k] = g2[3][k]/sqrt(g2[3][3])
    float winv = rsqrtf(gk[24]);
    float w[7];
#pragma unroll
    for (int k = 0; k < 7; k++) w[k] = gk[21 + k] * winv;

    // stage 0: load x tile with zero padding
    for (int i = tid; i < 40 * 40; i += 256) {
        int r = i / 40, c = i % 40;
        int gy = by - 4 + r, gx = bx - 4 + c;
        float v = 0.0f;
        if ((unsigned)gy < IMN && (unsigned)gx < IMN) v = x[gy * IMN + gx];
        sx[r][c] = v;
    }
    __syncthreads();

    // stage 1: Sobel (cross-correlation) on 38x38 region; zero outside image
    for (int i = tid; i < 38 * 38; i += 256) {
        int r = i / 38, c = i % 38;
        int gy = by - 3 + r, gx = bx - 3 + c;
        float ix = 0.0f, iy = 0.0f;
        if ((unsigned)gy < IMN && (unsigned)gx < IMN) {
            float a  = sx[r    ][c], b = sx[r    ][c + 1], cc = sx[r    ][c + 2];
            float d  = sx[r + 1][c],                       f  = sx[r + 1][c + 2];
            float g  = sx[r + 2][c], h = sx[r + 2][c + 1], i2 = sx[r + 2][c + 2];
            ix = (cc - a) + 2.0f * (f - d) + (i2 - g);
            iy = (g + 2.0f * h + i2) - (a + 2.0f * b + cc);
        }
        sIx[r][c] = ix;
        sIy[r][c] = iy;
    }
    __syncthreads();

    // stage 2: horizontal 7-tap gaussian of the 3 products
    for (int i = tid; i < 38 * 32; i += 256) {
        int r = i / 32, c = i % 32;
        float s0 = 0.0f, s1 = 0.0f, s2 = 0.0f;
#pragma unroll
        for (int k = 0; k < 7; k++) {
            float a = sIx[r][c + k], b = sIy[r][c + k], wk = w[k];
            s0 = fmaf(wk, a * a, s0);
            s1 = fmaf(wk, b * b, s1);
            s2 = fmaf(wk, a * b, s2);
        }
        sh[0][r][c] = s0; sh[1][r][c] = s1; sh[2][r][c] = s2;
    }
    __syncthreads();

    // stage 3: vertical 7-tap gaussian + Harris response
    const int tx = tid & 31, ty = tid >> 5;
#pragma unroll
    for (int j = 0; j < 4; j++) {
        int r = ty * 4 + j;
        float a0 = 0.0f, a1 = 0.0f, a2 = 0.0f;
#pragma unroll
        for (int k = 0; k < 7; k++) {
            float wk = w[k];
            a0 = fmaf(wk, sh[0][r + k][tx], a0);
            a1 = fmaf(wk, sh[1][r + k][tx], a1);
            a2 = fmaf(wk, sh[2][r + k][tx], a2);
        }
        float tr = a0 + a1;
        float R  = (a0 * a1 - a2 * a2) - 0.05f * tr * tr;
        g_R[(by + r) * IMN + (bx + tx)] = R;
    }
}

// ---------------- pass 1: 8192-bin smem-privatized histogram ----------------
__global__ __launch_bounds__(256) void k_hist1() {
    __shared__ unsigned h[8192];
    for (int b = threadIdx.x; b < 8192; b += 256) h[b] = 0u;
    __syncthreads();

    const float4* R4 = (const float4*)g_R;
    const int n4 = NPIX / 4;
    const int stride = gridDim.x * blockDim.x;
    for (int i = blockIdx.x * blockDim.x + threadIdx.x; i < n4; i += stride) {
        float4 v = R4[i];
        atomicAdd(&h[f2u(v.x) >> 19], 1u);
        atomicAdd(&h[f2u(v.y) >> 19], 1u);
        atomicAdd(&h[f2u(v.z) >> 19], 1u);
        atomicAdd(&h[f2u(v.w) >> 19], 1u);
    }
    __syncthreads();
    for (int b = threadIdx.x; b < 8192; b += 256) {
        unsigned c = h[b];
        if (c) atomicAdd(&g_hist13[b], c);
    }
}

// ---------------- parallel select over 8192 bins (single block) ------------
__global__ __launch_bounds__(256) void k_sel1() {
    const int tid = threadIdx.x;
    const unsigned rank = g_rank;

    unsigned cnt[32];
    unsigned s = 0u;
#pragma unroll
    for (int j = 0; j < 32; j++) { cnt[j] = g_hist13[tid * 32 + j]; s += cnt[j]; }

    unsigned v = s;
    const int lane = tid & 31, wid = tid >> 5;
#pragma unroll
    for (int o = 1; o < 32; o <<= 1) {
        unsigned t = __shfl_up_sync(0xFFFFFFFFu, v, o);
        if (lane >= o) v += t;
    }
    __shared__ unsigned wsum[8];
    if (lane == 31) wsum[wid] = v;
    __syncthreads();
    if (tid < 8) {
        unsigned t = wsum[tid];
#pragma unroll
        for (int o = 1; o < 8; o <<= 1) {
            unsigned q = __shfl_up_sync(0xFFu, t, o);
            if (tid >= o) t += q;
        }
        wsum[tid] = t;
    }
    __syncthreads();
    unsigned incl   = v + (wid ? wsum[wid - 1] : 0u);
    unsigned before = incl - s;

    if (s > 0u && rank >= before && rank < incl) {
        unsigned run = before;
#pragma unroll
        for (int j = 0; j < 32; j++) {
            if (rank < run + cnt[j]) {
                g_prefix = (unsigned)(tid * 32 + j);   // 13-bit bin value
                g_rank   = rank - run;
                break;
            }
            run += cnt[j];
        }
    }
}

// ---------------- pass 2: 2^19-bin global histogram over matching elems ----
__global__ __launch_bounds__(256) void k_hist19() {
    const unsigned pref = g_prefix;
    const float4* R4 = (const float4*)g_R;
    const int n4 = NPIX / 4;
    const int stride = gridDim.x * blockDim.x;
    for (int i = blockIdx.x * blockDim.x + threadIdx.x; i < n4; i += stride) {
        float4 v = R4[i];
        unsigned u;
        u = f2u(v.x); if ((u >> 19) == pref) atomicAdd(&g_hist19[u & 0x7FFFFu], 1u);
        u = f2u(v.y); if ((u >> 19) == pref) atomicAdd(&g_hist19[u & 0x7FFFFu], 1u);
        u = f2u(v.z); if ((u >> 19) == pref) atomicAdd(&g_hist19[u & 0x7FFFFu], 1u);
        u = f2u(v.w); if ((u >> 19) == pref) atomicAdd(&g_hist19[u & 0x7FFFFu], 1u);
    }
}

// ---------------- 19-bit select, level 1: 512 chunk sums of 1024 bins ------
__global__ __launch_bounds__(256) void k_sum19() {
    const int tid = threadIdx.x;
    unsigned base = blockIdx.x << 10;
    unsigned s = 0u;
#pragma unroll
    for (int j = 0; j < 4; j++) s += g_hist19[base + tid + j * 256];

    // warp + block reduce
#pragma unroll
    for (int o = 16; o > 0; o >>= 1) s += __shfl_down_sync(0xFFFFFFFFu, s, o);
    __shared__ unsigned ws[8];
    if ((tid & 31) == 0) ws[tid >> 5] = s;
    __syncthreads();
    if (tid == 0) {
        unsigned t = 0u;
#pragma unroll
        for (int j = 0; j < 8; j++) t += ws[j];
        g_chunk[blockIdx.x] = t;
    }
}

// ---------------- 19-bit select, level 2 (single block, 512 threads) -------
__global__ __launch_bounds__(512) void k_sel19() {
    const int tid = threadIdx.x;
    const int lane = tid & 31, wid = tid >> 5;
    const unsigned rank = g_rank;
    __shared__ unsigned wsum[16];
    __shared__ unsigned sh_chunk, sh_rank2;

    // phase 1: scan 512 chunk sums, locate chunk
    unsigned s = g_chunk[tid];
    unsigned v = s;
#pragma unroll
    for (int o = 1; o < 32; o <<= 1) {
        unsigned t = __shfl_up_sync(0xFFFFFFFFu, v, o);
        if (lane >= o) v += t;
    }
    if (lane == 31) wsum[wid] = v;
    __syncthreads();
    if (tid < 16) {
        unsigned t = wsum[tid];
#pragma unroll
        for (int o = 1; o < 16; o <<= 1) {
            unsigned q = __shfl_up_sync(0xFFFFu, t, o);
            if (tid >= o) t += q;
        }
        wsum[tid] = t;
    }
    __syncthreads();
    unsigned incl   = v + (wid ? wsum[wid - 1] : 0u);
    unsigned before = incl - s;
    if (s > 0u && rank >= before && rank < incl) {
        sh_chunk = (unsigned)tid;
        sh_rank2 = rank - before;
    }
    __syncthreads();

    // phase 2: scan the chosen 1024-bin chunk (2 bins/thread)
    const unsigned chunk = sh_chunk;
    const unsigned r2 = sh_rank2;
    const unsigned base = chunk << 10;
    unsigned c0 = g_hist19[base + 2 * tid];
    unsigned c1 = g_hist19[base + 2 * tid + 1];
    s = c0 + c1;
    v = s;
    __syncthreads();   // wsum reuse
#pragma unroll
    for (int o = 1; o < 32; o <<= 1) {
        unsigned t = __shfl_up_sync(0xFFFFFFFFu, v, o);
        if (lane >= o) v += t;
    }
    if (lane == 31) wsum[wid] = v;
    __syncthreads();
    if (tid < 16) {
        unsigned t = wsum[tid];
#pragma unroll
        for (int o = 1; o < 16; o <<= 1) {
            unsigned q = __shfl_up_sync(0xFFFFu, t, o);
            if (tid >= o) t += q;
        }
        wsum[tid] = t;
    }
    __syncthreads();
    incl   = v + (wid ? wsum[wid - 1] : 0u);
    before = incl - s;
    if (s > 0u && r2 >= before && r2 < incl) {
        unsigned bin19 = base + 2 * tid + ((r2 < before + c0) ? 0u : 1u);
        g_med = u2f((g_prefix << 19) | bin19);
    }
}

// ---------------- fused threshold + 7x7 NMS maxpool + mask ----------------
__global__ __launch_bounds__(256) void k_nms(float* __restrict__ out) {
    __shared__ float sr[38][40];
    __shared__ float hm[38][33];
    const int tid = threadIdx.x;
    const int bx = blockIdx.x * 32, by = blockIdx.y * 32;
    const float med = g_med;

    for (int i = tid; i < 38 * 38; i += 256) {
        int r = i / 38, c = i % 38;
        int gy = by - 3 + r, gx = bx - 3 + c;
        float v = -INFINITY;
        if ((unsigned)gy < IMN && (unsigned)gx < IMN) {
            float q = g_R[gy * IMN + gx];
            v = (q < med) ? 0.0f : q;
        }
        sr[r][c] = v;
    }
    __syncthreads();

    for (int i = tid; i < 38 * 32; i += 256) {
        int r = i / 32, c = i % 32;
        float m = sr[r][c];
#pragma unroll
        for (int k = 1; k < 7; k++) m = fmaxf(m, sr[r][c + k]);
        hm[r][c] = m;
    }
    __syncthreads();

    const int tx = tid & 31, ty = tid >> 5;
#pragma unroll
    for (int j = 0; j < 4; j++) {
        int r = ty * 4 + j;
        float m = hm[r][tx];
#pragma unroll
        for (int k = 1; k < 7; k++) m = fmaxf(m, hm[r + k][tx]);
        float ctr = sr[r + 3][tx + 3];
        out[(by + r) * IMN + (bx + tx)] = (ctr == m) ? ctr : 0.0f;
    }
}

// ---------------- launch ----------------
extern "C" void kernel_launch(void* const* d_in, const int* in_sizes, int n_in,
                              void* d_out, int out_size) {
    const float* x  = (const float*)d_in[0];
    const float* gk = (const float*)d_in[1];
    float* out = (float*)d_out;

    dim3 grid(IMN / 32, IMN / 32);

    k_init<<<512, 256>>>();
    k_R<<<grid, 256>>>(x, gk);
    k_hist1<<<1184, 256>>>();
    k_sel1<<<1, 256>>>();
    k_hist19<<<1184, 256>>>();
    k_sum19<<<512, 256>>>();
    k_sel19<<<1, 512>>>();
    k_nms<<<grid, 256>>>(out);
}

// round 4
// speedup vs baseline: 2.2569x; 1.0906x over previous
#include <cuda_runtime.h>
#include <math.h>

#define IMN 4096
#define NPIX (IMN*IMN)
#define MED_RANK 8388607u   /* (NPIX-1)/2 */

// ---------------- device scratch (no allocations allowed) ----------------
__device__ float    g_R[NPIX];            // Harris response
__device__ unsigned g_hist13[8192];       // pass-1 histogram (top 13 bits)
__device__ unsigned g_hist19[1 << 19];    // pass-2 histogram (low 19 bits)
__device__ unsigned g_chunk[512];         // chunk sums for 19-bit select
__device__ unsigned g_prefix;             // selected top-13-bit bin
__device__ unsigned g_rank;               // remaining rank
__device__ float    g_med;                // selected median value

// monotonic float<->uint order transform
__device__ __forceinline__ unsigned f2u(float f) {
    unsigned u = __float_as_uint(f);
    return (u & 0x80000000u) ? ~u : (u | 0x80000000u);
}
__device__ __forceinline__ float u2f(unsigned u) {
    return (u & 0x80000000u) ? __uint_as_float(u & 0x7fffffffu)
                             : __uint_as_float(~u);
}

// ---------------- init: zero both histograms ----------------
__global__ void k_init() {
    int gt = blockIdx.x * blockDim.x + threadIdx.x;
    int stride = gridDim.x * blockDim.x;
    for (int b = gt; b < (1 << 19); b += stride) g_hist19[b] = 0u;
    for (int b = gt; b < 8192; b += stride) g_hist13[b] = 0u;
    if (gt == 0) { g_prefix = 0u; g_rank = MED_RANK; g_med = 0.0f; }
}

// ---------------- fused Sobel + products + 7x7 Gaussian -> R ----------------
// 32x32 output tile, halo 4 (1 sobel + 3 gaussian). 256 threads.
// Sliding-window register reuse: each thread task produces 4 consecutive
// outputs from one windowed register load.
__global__ __launch_bounds__(256) void k_R(const float* __restrict__ x,
                                           const float* __restrict__ gk) {
    __shared__ float sx [40][41];
    __shared__ float sIx[38][39];
    __shared__ float sIy[38][39];
    __shared__ float sh [3][38][33];

    const int tid = threadIdx.x;
    const int bx = blockIdx.x * 32, by = blockIdx.y * 32;

    // 1D gaussian factors from provided 2D kernel: w[k] = g2[3][k]/sqrt(g2[3][3])
    float winv = rsqrtf(gk[24]);
    float w[7];
#pragma unroll
    for (int k = 0; k < 7; k++) w[k] = gk[21 + k] * winv;

    // stage 0: load x tile with zero padding
    for (int i = tid; i < 40 * 40; i += 256) {
        int r = i / 40, c = i % 40;
        int gy = by - 4 + r, gx = bx - 4 + c;
        float v = 0.0f;
        if ((unsigned)gy < IMN && (unsigned)gx < IMN) v = x[gy * IMN + gx];
        sx[r][c] = v;
    }
    __syncthreads();

    // stage 1: Sobel on 38x38 region; 4 consecutive cols per task
    for (int t = tid; t < 380; t += 256) {
        int r  = t % 38;
        int cb = (t / 38) * 4;
        int gy = by - 3 + r;
        bool rowok = (unsigned)gy < IMN;
        float r0[6], r1[6], r2[6];
#pragma unroll
        for (int j = 0; j < 6; j++) {
            int c = cb + j;
            bool ok = (c < 40);
            r0[j] = ok ? sx[r    ][c] : 0.0f;
            r1[j] = ok ? sx[r + 1][c] : 0.0f;
            r2[j] = ok ? sx[r + 2][c] : 0.0f;
        }
#pragma unroll
        for (int j = 0; j < 4; j++) {
            int c = cb + j;
            if (c < 38) {
                float ix = 0.0f, iy = 0.0f;
                int gx = bx - 3 + c;
                if (rowok && (unsigned)gx < IMN) {
                    ix = (r0[j+2] - r0[j]) + 2.0f*(r1[j+2] - r1[j]) + (r2[j+2] - r2[j]);
                    iy = (r2[j] + 2.0f*r2[j+1] + r2[j+2]) - (r0[j] + 2.0f*r0[j+1] + r0[j+2]);
                }
                sIx[r][c] = ix;
                sIy[r][c] = iy;
            }
        }
    }
    __syncthreads();

    // stage 2: horizontal 7-tap gaussian of products; 4 cols per task
    for (int t = tid; t < 304; t += 256) {
        int r  = t % 38;
        int cb = (t / 38) * 4;          // 0..28
        float px[10], py[10], pxy[10];
#pragma unroll
        for (int j = 0; j < 10; j++) {
            float a = sIx[r][cb + j], b = sIy[r][cb + j];
            px[j] = a * a; py[j] = b * b; pxy[j] = a * b;
        }
#pragma unroll
        for (int j = 0; j < 4; j++) {
            float s0 = 0.0f, s1 = 0.0f, s2 = 0.0f;
#pragma unroll
            for (int k = 0; k < 7; k++) {
                float wk = w[k];
                s0 = fmaf(wk, px [j + k], s0);
                s1 = fmaf(wk, py [j + k], s1);
                s2 = fmaf(wk, pxy[j + k], s2);
            }
            sh[0][r][cb + j] = s0;
            sh[1][r][cb + j] = s1;
            sh[2][r][cb + j] = s2;
        }
    }
    __syncthreads();

    // stage 3: vertical 7-tap gaussian + Harris response, register rolling
    {
        const int tx = tid & 31, r0 = (tid >> 5) * 4;
        float a0r[10], a1r[10], a2r[10];
#pragma unroll
        for (int i = 0; i < 10; i++) {
            a0r[i] = sh[0][r0 + i][tx];
            a1r[i] = sh[1][r0 + i][tx];
            a2r[i] = sh[2][r0 + i][tx];
        }
#pragma unroll
        for (int j = 0; j < 4; j++) {
            float a0 = 0.0f, a1 = 0.0f, a2 = 0.0f;
#pragma unroll
            for (int k = 0; k < 7; k++) {
                float wk = w[k];
                a0 = fmaf(wk, a0r[j + k], a0);
                a1 = fmaf(wk, a1r[j + k], a1);
                a2 = fmaf(wk, a2r[j + k], a2);
            }
            float tr = a0 + a1;
            float R  = (a0 * a1 - a2 * a2) - 0.05f * tr * tr;
            g_R[(by + r0 + j) * IMN + (bx + tx)] = R;
        }
    }
}

// ---------------- pass 1: 8192-bin smem-privatized histogram ----------------
__global__ __launch_bounds__(256) void k_hist1() {
    __shared__ unsigned h[8192];
    for (int b = threadIdx.x; b < 8192; b += 256) h[b] = 0u;
    __syncthreads();

    const float4* R4 = (const float4*)g_R;
    const int n4 = NPIX / 4;
    const int stride = gridDim.x * blockDim.x;
    for (int i = blockIdx.x * blockDim.x + threadIdx.x; i < n4; i += stride) {
        float4 v = R4[i];
        atomicAdd(&h[f2u(v.x) >> 19], 1u);
        atomicAdd(&h[f2u(v.y) >> 19], 1u);
        atomicAdd(&h[f2u(v.z) >> 19], 1u);
        atomicAdd(&h[f2u(v.w) >> 19], 1u);
    }
    __syncthreads();
    for (int b = threadIdx.x; b < 8192; b += 256) {
        unsigned c = h[b];
        if (c) atomicAdd(&g_hist13[b], c);
    }
}

// ---------------- parallel select over 8192 bins (single block, 1024 thr) --
__global__ __launch_bounds__(1024) void k_sel1() {
    const int tid = threadIdx.x;
    const unsigned rank = g_rank;

    unsigned cnt[8];
    unsigned s = 0u;
#pragma unroll
    for (int j = 0; j < 8; j++) { cnt[j] = g_hist13[tid * 8 + j]; s += cnt[j]; }

    unsigned v = s;
    const int lane = tid & 31, wid = tid >> 5;
#pragma unroll
    for (int o = 1; o < 32; o <<= 1) {
        unsigned t = __shfl_up_sync(0xFFFFFFFFu, v, o);
        if (lane >= o) v += t;
    }
    __shared__ unsigned wsum[32];
    if (lane == 31) wsum[wid] = v;
    __syncthreads();
    if (tid < 32) {
        unsigned t = wsum[tid];
#pragma unroll
        for (int o = 1; o < 32; o <<= 1) {
            unsigned q = __shfl_up_sync(0xFFFFFFFFu, t, o);
            if (tid >= o) t += q;
        }
        wsum[tid] = t;
    }
    __syncthreads();
    unsigned incl   = v + (wid ? wsum[wid - 1] : 0u);
    unsigned before = incl - s;

    if (s > 0u && rank >= before && rank < incl) {
        unsigned run = before;
#pragma unroll
        for (int j = 0; j < 8; j++) {
            if (rank < run + cnt[j]) {
                g_prefix = (unsigned)(tid * 8 + j);   // 13-bit bin value
                g_rank   = rank - run;
                break;
            }
            run += cnt[j];
        }
    }
}

// ---------------- pass 2: 2^19-bin global histogram over matching elems ----
__global__ __launch_bounds__(256) void k_hist19() {
    const unsigned pref = g_prefix;
    const float4* R4 = (const float4*)g_R;
    const int n4 = NPIX / 4;
    const int stride = gridDim.x * blockDim.x;
    for (int i = blockIdx.x * blockDim.x + threadIdx.x; i < n4; i += stride) {
        float4 v = R4[i];
        unsigned u;
        u = f2u(v.x); if ((u >> 19) == pref) atomicAdd(&g_hist19[u & 0x7FFFFu], 1u);
        u = f2u(v.y); if ((u >> 19) == pref) atomicAdd(&g_hist19[u & 0x7FFFFu], 1u);
        u = f2u(v.z); if ((u >> 19) == pref) atomicAdd(&g_hist19[u & 0x7FFFFu], 1u);
        u = f2u(v.w); if ((u >> 19) == pref) atomicAdd(&g_hist19[u & 0x7FFFFu], 1u);
    }
}

// ---------------- 19-bit select, level 1: 512 chunk sums of 1024 bins ------
__global__ __launch_bounds__(256) void k_sum19() {
    const int tid = threadIdx.x;
    unsigned base = blockIdx.x << 10;
    unsigned s = 0u;
#pragma unroll
    for (int j = 0; j < 4; j++) s += g_hist19[base + tid + j * 256];

#pragma unroll
    for (int o = 16; o > 0; o >>= 1) s += __shfl_down_sync(0xFFFFFFFFu, s, o);
    __shared__ unsigned ws[8];
    if ((tid & 31) == 0) ws[tid >> 5] = s;
    __syncthreads();
    if (tid == 0) {
        unsigned t = 0u;
#pragma unroll
        for (int j = 0; j < 8; j++) t += ws[j];
        g_chunk[blockIdx.x] = t;
    }
}

// ---------------- 19-bit select, level 2 (single block, 512 threads) -------
__global__ __launch_bounds__(512) void k_sel19() {
    const int tid = threadIdx.x;
    const int lane = tid & 31, wid = tid >> 5;
    const unsigned rank = g_rank;
    __shared__ unsigned wsum[16];
    __shared__ unsigned sh_chunk, sh_rank2;

    // phase 1: scan 512 chunk sums, locate chunk
    unsigned s = g_chunk[tid];
    unsigned v = s;
#pragma unroll
    for (int o = 1; o < 32; o <<= 1) {
        unsigned t = __shfl_up_sync(0xFFFFFFFFu, v, o);
        if (lane >= o) v += t;
    }
    if (lane == 31) wsum[wid] = v;
    __syncthreads();
    if (tid < 16) {
        unsigned t = wsum[tid];
#pragma unroll
        for (int o = 1; o < 16; o <<= 1) {
            unsigned q = __shfl_up_sync(0xFFFFu, t, o);
            if (tid >= o) t += q;
        }
        wsum[tid] = t;
    }
    __syncthreads();
    unsigned incl   = v + (wid ? wsum[wid - 1] : 0u);
    unsigned before = incl - s;
    if (s > 0u && rank >= before && rank < incl) {
        sh_chunk = (unsigned)tid;
        sh_rank2 = rank - before;
    }
    __syncthreads();

    // phase 2: scan the chosen 1024-bin chunk (2 bins/thread)
    const unsigned chunk = sh_chunk;
    const unsigned r2 = sh_rank2;
    const unsigned base = chunk << 10;
    unsigned c0 = g_hist19[base + 2 * tid];
    unsigned c1 = g_hist19[base + 2 * tid + 1];
    s = c0 + c1;
    v = s;
    __syncthreads();   // wsum reuse
#pragma unroll
    for (int o = 1; o < 32; o <<= 1) {
        unsigned t = __shfl_up_sync(0xFFFFFFFFu, v, o);
        if (lane >= o) v += t;
    }
    if (lane == 31) wsum[wid] = v;
    __syncthreads();
    if (tid < 16) {
        unsigned t = wsum[tid];
#pragma unroll
        for (int o = 1; o < 16; o <<= 1) {
            unsigned q = __shfl_up_sync(0xFFFFu, t, o);
            if (tid >= o) t += q;
        }
        wsum[tid] = t;
    }
    __syncthreads();
    incl   = v + (wid ? wsum[wid - 1] : 0u);
    before = incl - s;
    if (s > 0u && r2 >= before && r2 < incl) {
        unsigned bin19 = base + 2 * tid + ((r2 < before + c0) ? 0u : 1u);
        g_med = u2f((g_prefix << 19) | bin19);
    }
}

// ---------------- fused threshold + 7x7 NMS maxpool + mask ----------------
__global__ __launch_bounds__(256) void k_nms(float* __restrict__ out) {
    __shared__ float sr[38][41];
    __shared__ float hm[38][33];
    const int tid = threadIdx.x;
    const int bx = blockIdx.x * 32, by = blockIdx.y * 32;
    const float med = g_med;

    for (int i = tid; i < 38 * 38; i += 256) {
        int r = i / 38, c = i % 38;
        int gy = by - 3 + r, gx = bx - 3 + c;
        float v = -INFINITY;
        if ((unsigned)gy < IMN && (unsigned)gx < IMN) {
            float q = g_R[gy * IMN + gx];
            v = (q < med) ? 0.0f : q;
        }
        sr[r][c] = v;
    }
    __syncthreads();

    // horizontal 7-max, 4 cols per task (sliding window)
    for (int t = tid; t < 304; t += 256) {
        int r  = t % 38;
        int cb = (t / 38) * 4;          // 0..28
        float wv[10];
#pragma unroll
        for (int j = 0; j < 10; j++) wv[j] = sr[r][cb + j];
        float tmax[9], q[7];
#pragma unroll
        for (int j = 0; j < 9; j++) tmax[j] = fmaxf(wv[j], wv[j + 1]);
#pragma unroll
        for (int j = 0; j < 7; j++) q[j] = fmaxf(tmax[j], tmax[j + 2]);
#pragma unroll
        for (int j = 0; j < 4; j++) hm[r][cb + j] = fmaxf(q[j], q[j + 3]);
    }
    __syncthreads();

    // vertical 7-max + mask
    {
        const int tx = tid & 31, r0 = (tid >> 5) * 4;
        float wv[10];
#pragma unroll
        for (int i = 0; i < 10; i++) wv[i] = hm[r0 + i][tx];
        float tmax[9], q[7];
#pragma unroll
        for (int j = 0; j < 9; j++) tmax[j] = fmaxf(wv[j], wv[j + 1]);
#pragma unroll
        for (int j = 0; j < 7; j++) q[j] = fmaxf(tmax[j], tmax[j + 2]);
#pragma unroll
        for (int j = 0; j < 4; j++) {
            float m   = fmaxf(q[j], q[j + 3]);
            float ctr = sr[r0 + 3 + j][tx + 3];
            out[(by + r0 + j) * IMN + (bx + tx)] = (ctr == m) ? ctr : 0.0f;
        }
    }
}

// ---------------- launch ----------------
extern "C" void kernel_launch(void* const* d_in, const int* in_sizes, int n_in,
                              void* d_out, int out_size) {
    const float* x  = (const float*)d_in[0];
    const float* gk = (const float*)d_in[1];
    float* out = (float*)d_out;

    dim3 grid(IMN / 32, IMN / 32);

    k_init<<<512, 256>>>();
    k_R<<<grid, 256>>>(x, gk);
    k_hist1<<<1184, 256>>>();
    k_sel1<<<1, 1024>>>();
    k_hist19<<<1184, 256>>>();
    k_sum19<<<512, 256>>>();
    k_sel19<<<1, 512>>>();
    k_nms<<<grid, 256>>>(out);
}